// round 15
// baseline (speedup 1.0000x reference)
#include <cuda_runtime.h>
#include <cuda_fp16.h>
#include <cstdint>
#include <float.h>

#define NTOK 2048
#define DM   1024
#define NH   16
#define HD   64

// ---------------------------------------------------------------------------
// Scratch (__device__ globals; allocation-free rule)
// ---------------------------------------------------------------------------
__device__ __half g_xf[NTOK * DM];            // x in fp16
__device__ __half g_Qf[NTOK * DM];            // pre-scaled by 0.125*log2e
__device__ __half g_Kf[NTOK * DM];
__device__ __half g_Vf[NTOK * DM];
__device__ __half g_Of[NTOK * DM];            // attention output in fp16
// weights in fp16, ORIGINAL [K,N] layout
__device__ __half g_Wqf[DM * DM], g_Wkf[DM * DM], g_Wvf[DM * DM], g_Wof[DM * DM];

// ---------------------------------------------------------------------------
// PTX helpers (base-target tensor path; tcgen05 unavailable at compute_103)
// ---------------------------------------------------------------------------
__device__ __forceinline__ uint32_t smem_u32(const void* p) {
    uint32_t a;
    asm("{ .reg .u64 t; cvta.to.shared.u64 t, %1; cvt.u32.u64 %0, t; }" : "=r"(a) : "l"(p));
    return a;
}

__device__ __forceinline__ float ex2f(float x) {   // MUFU.EX2 (2^x)
    float r;
    asm("ex2.approx.ftz.f32 %0, %1;" : "=f"(r) : "f"(x));
    return r;
}

#define LDMATRIX_X4(r0, r1, r2, r3, addr) \
    asm volatile("ldmatrix.sync.aligned.m8n8.x4.shared.b16 {%0,%1,%2,%3}, [%4];" \
                 : "=r"(r0), "=r"(r1), "=r"(r2), "=r"(r3) : "r"(addr))
#define LDMATRIX_X4T(r0, r1, r2, r3, addr) \
    asm volatile("ldmatrix.sync.aligned.m8n8.x4.trans.shared.b16 {%0,%1,%2,%3}, [%4];" \
                 : "=r"(r0), "=r"(r1), "=r"(r2), "=r"(r3) : "r"(addr))
#define MMA_F16(d, a, b) \
    asm volatile("mma.sync.aligned.m16n8k16.row.col.f32.f16.f16.f32 " \
                 "{%0,%1,%2,%3}, {%4,%5,%6,%7}, {%8,%9}, {%0,%1,%2,%3};" \
                 : "+f"((d)[0]), "+f"((d)[1]), "+f"((d)[2]), "+f"((d)[3]) \
                 : "r"((a)[0]), "r"((a)[1]), "r"((a)[2]), "r"((a)[3]), \
                   "r"((b)[0]), "r"((b)[1]))

#define CP_ASYNC16(dst, src) \
    asm volatile("cp.async.cg.shared.global [%0], [%1], 16;" :: "r"(dst), "l"(src) : "memory")
#define CP_COMMIT() asm volatile("cp.async.commit_group;" ::: "memory")
#define CP_WAIT1()  asm volatile("cp.async.wait_group 1;" ::: "memory")

__device__ __forceinline__ uint32_t pack_h2(float a, float b) {
    __half2 t = __floats2half2_rn(a, b);
    return *reinterpret_cast<uint32_t*>(&t);
}

// 0.125 * log2(e): folded into Q so softmax runs in exp2 domain
#define QSCALE 0.18033688011112042f

// ---------------------------------------------------------------------------
// Fused fp32 -> fp16 conversion: z=0 -> x (2M elems), z=1..4 -> weights (1M).
// ---------------------------------------------------------------------------
__global__ __launch_bounds__(256)
void convert_all(const float* __restrict__ x,
                 const float* __restrict__ W0, const float* __restrict__ W1,
                 const float* __restrict__ W2, const float* __restrict__ W3,
                 __half* __restrict__ xf,
                 __half* __restrict__ T0, __half* __restrict__ T1,
                 __half* __restrict__ T2, __half* __restrict__ T3)
{
    const int z = blockIdx.z;
    if (z > 0 && blockIdx.x >= DM * DM / 1024) return;   // weights: 1M elems only
    const float* S = (z == 0) ? x : (z == 1) ? W0 : (z == 2) ? W1 : (z == 3) ? W2 : W3;
    __half* D      = (z == 0) ? xf : (z == 1) ? T0 : (z == 2) ? T1 : (z == 3) ? T2 : T3;
    int i4 = blockIdx.x * 256 + threadIdx.x;
    float4 v = reinterpret_cast<const float4*>(S)[i4];
    uint2 o;
    o.x = pack_h2(v.x, v.y);
    o.y = pack_h2(v.z, v.w);
    reinterpret_cast<uint2*>(D)[i4] = o;
}

// ---------------------------------------------------------------------------
// fp16 GEMM via mma.sync + 3-stage cp.async pipeline.
// C = A[M,K] @ B + bias, B in [K,N] layout (fragments via ldmatrix.trans).
// 128(M) x 64(N) CTA tile, BK=32, 256 threads = 8 warps (4M x 2N, 32x32 warp
// tile). 2 CTAs/SM. z selects (B, bias, out); z==0 (Q) scaled by QSCALE.
// ---------------------------------------------------------------------------
#define ASTRIDE 40                        // halfs per A smem row (32 + 8 pad)
#define ABYTES  (128 * ASTRIDE * 2)       // 10240
#define BSTRIDE 72                        // halfs per B smem row (64 + 8 pad)
#define BBYTES  (32 * BSTRIDE * 2)        // 4608
#define STAGEB  (ABYTES + BBYTES)         // 14848
#define NSTAGE  3                         // 44544 B static smem

template<bool F32OUT>
__global__ __launch_bounds__(256, 2)
void gemm_f16(const __half* __restrict__ A,
              const __half* __restrict__ B0, const __half* __restrict__ B1,
              const __half* __restrict__ B2,
              const float* __restrict__ bias0, const float* __restrict__ bias1,
              const float* __restrict__ bias2,
              __half* __restrict__ Ch0, __half* __restrict__ Ch1,
              __half* __restrict__ Ch2, float* __restrict__ Cf)
{
    __shared__ __align__(16) char sm[NSTAGE * STAGEB];

    const int z = blockIdx.z;
    const __half* B    = (z == 0) ? B0 : (z == 1) ? B1 : B2;
    const float* bias  = (z == 0) ? bias0 : (z == 1) ? bias1 : bias2;
    __half* Ch         = (z == 0) ? Ch0 : (z == 1) ? Ch1 : Ch2;
    const float osc    = (!F32OUT && z == 0) ? QSCALE : 1.0f;

    const int tid  = threadIdx.x;
    const int wid  = tid >> 5, lane = tid & 31;
    const int wm   = wid >> 1, wn = wid & 1;          // 4 x 2 warp grid
    const int col0 = blockIdx.x * 64;                 // N
    const int row0 = blockIdx.y * 128;                // M

    const uint32_t sbase = smem_u32(sm);

    // A staging: 512 16B-chunks; thread t -> chunks t and t+256
    const int at_r0 = (tid + 0)   >> 2, at_c0 = ((tid + 0)   & 3) << 3;
    const int at_r1 = (tid + 256) >> 2, at_c1 = ((tid + 256) & 3) << 3;
    const __half* Ap0 = A + (size_t)(row0 + at_r0) * DM + at_c0;
    const __half* Ap1 = A + (size_t)(row0 + at_r1) * DM + at_c1;
    const uint32_t ad0 = (uint32_t)(at_r0 * ASTRIDE + at_c0) * 2;
    const uint32_t ad1 = (uint32_t)(at_r1 * ASTRIDE + at_c1) * 2;

    // B staging: 256 16B-chunks; thread t -> chunk t (kr = t>>3, c8 = (t&7)*8)
    const int bt_r = tid >> 3;
    const int bt_c = (tid & 7) << 3;
    const __half* Bp = B + (size_t)bt_r * DM + col0 + bt_c;
    const uint32_t bd = (uint32_t)(bt_r * BSTRIDE + bt_c) * 2;

    // prologue: prefill stages 0, 1
    {
        CP_ASYNC16(sbase + 0 * STAGEB + ad0,          Ap0);
        CP_ASYNC16(sbase + 0 * STAGEB + ad1,          Ap1);
        CP_ASYNC16(sbase + 0 * STAGEB + ABYTES + bd,  Bp);
        CP_COMMIT();
        CP_ASYNC16(sbase + 1 * STAGEB + ad0,          Ap0 + 32);
        CP_ASYNC16(sbase + 1 * STAGEB + ad1,          Ap1 + 32);
        CP_ASYNC16(sbase + 1 * STAGEB + ABYTES + bd,  Bp + (size_t)32 * DM);
        CP_COMMIT();
    }

    // fragment offsets
    const int aRow  = wm * 32 + (lane & 15);
    const int aK8   = (lane >> 4) << 3;
    const int bRowL = lane & 15;
    const int bC8   = (lane >> 4) << 3;

    float acc[2][4][4] = {};

    #pragma unroll 1
    for (int c = 0; c < DM / 32; c++) {
        CP_WAIT1();
        __syncthreads();

        const uint32_t sA = sbase + (c % NSTAGE) * STAGEB;
        const uint32_t sB = sA + ABYTES;

        #pragma unroll
        for (int ks = 0; ks < 32; ks += 16) {
            uint32_t bf[8];
            #pragma unroll
            for (int g = 0; g < 2; g++) {
                uint32_t off = sB + (uint32_t)(((ks + bRowL) * BSTRIDE
                                 + wn * 32 + g * 16 + bC8) * 2);
                LDMATRIX_X4T(bf[4 * g], bf[4 * g + 1], bf[4 * g + 2], bf[4 * g + 3], off);
            }
            #pragma unroll
            for (int mt = 0; mt < 2; mt++) {
                uint32_t af[4];
                uint32_t off = sA + (uint32_t)(((aRow + mt * 16) * ASTRIDE + ks + aK8) * 2);
                LDMATRIX_X4(af[0], af[1], af[2], af[3], off);
                #pragma unroll
                for (int nt = 0; nt < 4; nt++) MMA_F16(acc[mt][nt], af, &bf[nt * 2]);
            }
        }

        // issue stage c+2 (buffer (c+2)%3 == (c-1)%3: all warps are past the
        // sync of this iteration, so no one still reads chunk c-1)
        if (c + 2 < DM / 32) {
            const int kn = (c + 2) * 32;
            const uint32_t sD = sbase + ((c + 2) % NSTAGE) * STAGEB;
            CP_ASYNC16(sD + ad0,         Ap0 + kn);
            CP_ASYNC16(sD + ad1,         Ap1 + kn);
            CP_ASYNC16(sD + ABYTES + bd, Bp + (size_t)kn * DM);
        }
        CP_COMMIT();
    }

    // epilogue
    const int qr = lane >> 2, qc = (lane & 3) << 1;
    #pragma unroll
    for (int nt = 0; nt < 4; nt++) {
        const int col = col0 + wn * 32 + nt * 8 + qc;
        const float2 bb = *reinterpret_cast<const float2*>(&bias[col]);
        #pragma unroll
        for (int mt = 0; mt < 2; mt++) {
            const int r = row0 + wm * 32 + mt * 16 + qr;
            float v00 = (acc[mt][nt][0] + bb.x) * osc, v01 = (acc[mt][nt][1] + bb.y) * osc;
            float v10 = (acc[mt][nt][2] + bb.x) * osc, v11 = (acc[mt][nt][3] + bb.y) * osc;
            if (F32OUT) {
                float2 o0 = { v00, v01 }, o1 = { v10, v11 };
                *reinterpret_cast<float2*>(&Cf[(size_t)r * DM + col])       = o0;
                *reinterpret_cast<float2*>(&Cf[(size_t)(r + 8) * DM + col]) = o1;
            } else {
                *reinterpret_cast<uint32_t*>(&Ch[(size_t)r * DM + col])       = pack_h2(v00, v01);
                *reinterpret_cast<uint32_t*>(&Ch[(size_t)(r + 8) * DM + col]) = pack_h2(v10, v11);
            }
        }
    }
}

// ---------------------------------------------------------------------------
// fp16 flash attention (causal), exp2-domain softmax (Q pre-scaled).
// CTA = 64 q-rows x 1 head, 128 threads (4 warps x 16 rows); K-tile = 64.
// Dense/diagonal split: tiles kb < qb have NO masks or predicates.
// ---------------------------------------------------------------------------
#define FSTR 72   // smem row stride (halfs)
#define F_Q        0
#define F_K(b)     ((64  + (b) * 128) * FSTR)
#define F_V(b)     ((128 + (b) * 128) * FSTR)
#define F_SMEM_B   (320 * FSTR * 2)   // 46080 B

template<bool DIAG>
__device__ __forceinline__ void fa_tile(
    const int kb, const int warpR, const int lane,
    const uint32_t (&qf)[4][4], const uint32_t sK, const uint32_t sV,
    float (&o)[8][4], float& m0, float& m1, float& l0, float& l1)
{
    // ---- S = Q K^T (16 x 64 per warp) ----
    float s[8][4];
    #pragma unroll
    for (int nt = 0; nt < 8; nt++) {
        float init = 0.f;
        if (DIAG) init = ((kb * 64 + nt * 8) <= (warpR + 15)) ? 0.f : -1e30f;
        s[nt][0] = init; s[nt][1] = init; s[nt][2] = init; s[nt][3] = init;
    }

    #pragma unroll
    for (int kc = 0; kc < 4; kc++) {
        uint32_t kf[16];
        #pragma unroll
        for (int np = 0; np < 4; np++) {
            if (!DIAG || (kb * 64 + np * 16) <= (warpR + 15)) {
                uint32_t off = sK + (uint32_t)(((np * 16 + ((lane >> 4) << 3) + (lane & 7)) * FSTR
                                 + kc * 16 + (((lane >> 3) & 1) << 3)) * 2);
                LDMATRIX_X4(kf[4 * np], kf[4 * np + 1], kf[4 * np + 2], kf[4 * np + 3], off);
            }
        }
        #pragma unroll
        for (int nt = 0; nt < 8; nt++)
            if (!DIAG || (kb * 64 + nt * 8) <= (warpR + 15))
                MMA_F16(s[nt], qf[kc], &kf[nt * 2]);
    }

    // ---- causal mask (diagonal tile only) ----
    if (DIAG) {
        #pragma unroll
        for (int nt = 0; nt < 8; nt++) {
            if ((kb * 64 + nt * 8) <= (warpR + 15)) {
                const int colg = kb * 64 + nt * 8 + ((lane & 3) << 1);
                const int r0g  = warpR + (lane >> 2);
                #pragma unroll
                for (int j = 0; j < 4; j++) {
                    int colj = colg + (j & 1);
                    int rowj = r0g + ((j >> 1) << 3);
                    if (colj > rowj) s[nt][j] = -1e30f;
                }
            }
        }
    }

    // ---- online softmax, log2 domain ----
    float rm0 = -1e30f, rm1 = -1e30f;
    #pragma unroll
    for (int nt = 0; nt < 8; nt++) {
        rm0 = fmaxf(rm0, fmaxf(s[nt][0], s[nt][1]));
        rm1 = fmaxf(rm1, fmaxf(s[nt][2], s[nt][3]));
    }
    rm0 = fmaxf(rm0, __shfl_xor_sync(0xffffffffu, rm0, 1));
    rm0 = fmaxf(rm0, __shfl_xor_sync(0xffffffffu, rm0, 2));
    rm1 = fmaxf(rm1, __shfl_xor_sync(0xffffffffu, rm1, 1));
    rm1 = fmaxf(rm1, __shfl_xor_sync(0xffffffffu, rm1, 2));

    const float mn0 = fmaxf(m0, rm0), mn1 = fmaxf(m1, rm1);
    const float cr0 = ex2f(m0 - mn0), cr1 = ex2f(m1 - mn1);
    m0 = mn0; m1 = mn1;

    float rs0 = 0.f, rs1 = 0.f;
    #pragma unroll
    for (int nt = 0; nt < 8; nt++) {
        s[nt][0] = ex2f(s[nt][0] - mn0);
        s[nt][1] = ex2f(s[nt][1] - mn0);
        s[nt][2] = ex2f(s[nt][2] - mn1);
        s[nt][3] = ex2f(s[nt][3] - mn1);
        rs0 += s[nt][0] + s[nt][1];
        rs1 += s[nt][2] + s[nt][3];
    }
    rs0 += __shfl_xor_sync(0xffffffffu, rs0, 1);
    rs0 += __shfl_xor_sync(0xffffffffu, rs0, 2);
    rs1 += __shfl_xor_sync(0xffffffffu, rs1, 1);
    rs1 += __shfl_xor_sync(0xffffffffu, rs1, 2);
    l0 = l0 * cr0 + rs0;
    l1 = l1 * cr1 + rs1;

    #pragma unroll
    for (int nt = 0; nt < 8; nt++) {
        o[nt][0] *= cr0; o[nt][1] *= cr0;
        o[nt][2] *= cr1; o[nt][3] *= cr1;
    }

    // ---- O += P V ----
    #pragma unroll
    for (int kc = 0; kc < 4; kc++) {
        if (!DIAG || (kb * 64 + kc * 16) <= (warpR + 15)) {
            uint32_t pf[4];
            pf[0] = pack_h2(s[2 * kc][0],     s[2 * kc][1]);
            pf[1] = pack_h2(s[2 * kc][2],     s[2 * kc][3]);
            pf[2] = pack_h2(s[2 * kc + 1][0], s[2 * kc + 1][1]);
            pf[3] = pack_h2(s[2 * kc + 1][2], s[2 * kc + 1][3]);

            uint32_t vf[16];
            #pragma unroll
            for (int np = 0; np < 4; np++) {
                uint32_t off = sV + (uint32_t)(((kc * 16 + (lane & 15)) * FSTR
                                 + np * 16 + ((lane >> 4) << 3)) * 2);
                LDMATRIX_X4T(vf[4 * np], vf[4 * np + 1], vf[4 * np + 2], vf[4 * np + 3], off);
            }
            #pragma unroll
            for (int nt = 0; nt < 8; nt++) MMA_F16(o[nt], pf, &vf[nt * 2]);
        }
    }
}

__global__ __launch_bounds__(128, 2)
void flash_f16(const __half* __restrict__ Qg, const __half* __restrict__ Kg,
               const __half* __restrict__ Vg, __half* __restrict__ Og)
{
    extern __shared__ __half fsm[];

    const int h     = blockIdx.x;
    const int qb    = 31 - blockIdx.y;     // big tiles first
    const int tid   = threadIdx.x;
    const int wid   = tid >> 5, lane = tid & 31;
    const int cb    = h * HD;
    const int row0  = qb * 64;
    const int kbmax = qb;                  // diagonal tile index
    const int warpR = row0 + wid * 16;

    const uint32_t sb = smem_u32(fsm);
    char* smc = reinterpret_cast<char*>(fsm);

    size_t   gkv[4];
    uint32_t kvd[4];
    #pragma unroll
    for (int s = 0; s < 4; s++) {
        int vid = tid + 128 * s;
        int r = vid >> 3, c8 = (vid & 7) << 3;
        gkv[s] = (size_t)r * DM + cb + c8;
        kvd[s] = (uint32_t)(r * FSTR + c8) * 2;
    }

    // stage Q tile
    #pragma unroll
    for (int s = 0; s < 4; s++) {
        uint4 v = *reinterpret_cast<const uint4*>(Qg + (size_t)row0 * DM + gkv[s]);
        *reinterpret_cast<uint4*>(smc + F_Q * 2 + kvd[s]) = v;
    }

    // stage K/V tile 0 into buffer 0
    uint4 pk[4], pv[4];
    #pragma unroll
    for (int s = 0; s < 4; s++) {
        pk[s] = *reinterpret_cast<const uint4*>(Kg + gkv[s]);
        pv[s] = *reinterpret_cast<const uint4*>(Vg + gkv[s]);
    }
    #pragma unroll
    for (int s = 0; s < 4; s++) {
        *reinterpret_cast<uint4*>(smc + F_K(0) * 2 + kvd[s]) = pk[s];
        *reinterpret_cast<uint4*>(smc + F_V(0) * 2 + kvd[s]) = pv[s];
    }
    __syncthreads();

    // Q fragments
    uint32_t qf[4][4];
    {
        uint32_t off = sb + F_Q * 2
            + (uint32_t)(((wid * 16 + (lane & 15)) * FSTR + ((lane >> 4) << 3)) * 2);
        #pragma unroll
        for (int kc = 0; kc < 4; kc++)
            LDMATRIX_X4(qf[kc][0], qf[kc][1], qf[kc][2], qf[kc][3], off + kc * 32);
    }

    float m0 = -1e30f, m1 = -1e30f, l0 = 0.f, l1 = 0.f;
    float o[8][4] = {};

    // dense tiles: no masks, no predicates
    #pragma unroll 1
    for (int kb = 0; kb < kbmax; kb++) {
        const size_t nb = (size_t)((kb + 1) * 64) * DM;
        #pragma unroll
        for (int s = 0; s < 4; s++) {
            pk[s] = *reinterpret_cast<const uint4*>(Kg + nb + gkv[s]);
            pv[s] = *reinterpret_cast<const uint4*>(Vg + nb + gkv[s]);
        }

        fa_tile<false>(kb, warpR, lane, qf,
                       sb + F_K(kb & 1) * 2, sb + F_V(kb & 1) * 2,
                       o, m0, m1, l0, l1);

        char* dk = smc + F_K((kb + 1) & 1) * 2;
        char* dv = smc + F_V((kb + 1) & 1) * 2;
        #pragma unroll
        for (int s2 = 0; s2 < 4; s2++) {
            *reinterpret_cast<uint4*>(dk + kvd[s2]) = pk[s2];
            *reinterpret_cast<uint4*>(dv + kvd[s2]) = pv[s2];
        }
        __syncthreads();
    }

    // diagonal tile
    fa_tile<true>(kbmax, warpR, lane, qf,
                  sb + F_K(kbmax & 1) * 2, sb + F_V(kbmax & 1) * 2,
                  o, m0, m1, l0, l1);

    // ---- epilogue: fp16 output ----
    const float inv0 = 1.f / l0, inv1 = 1.f / l1;
    const int r0g = warpR + (lane >> 2);
    #pragma unroll
    for (int nt = 0; nt < 8; nt++) {
        const int col = cb + nt * 8 + ((lane & 3) << 1);
        *reinterpret_cast<uint32_t*>(&Og[(size_t)r0g * DM + col]) =
            pack_h2(o[nt][0] * inv0, o[nt][1] * inv0);
        *reinterpret_cast<uint32_t*>(&Og[(size_t)(r0g + 8) * DM + col]) =
            pack_h2(o[nt][2] * inv1, o[nt][3] * inv1);
    }
}

// ---------------------------------------------------------------------------
// Launch
// ---------------------------------------------------------------------------
extern "C" void kernel_launch(void* const* d_in, const int* in_sizes, int n_in,
                              void* d_out, int out_size)
{
    const float* x  = (const float*)d_in[0];
    const float* Wq = (const float*)d_in[1];
    const float* bq = (const float*)d_in[2];
    const float* Wk = (const float*)d_in[3];
    const float* bk = (const float*)d_in[4];
    const float* Wv = (const float*)d_in[5];
    const float* bv = (const float*)d_in[6];
    const float* Wo = (const float*)d_in[7];
    const float* bo = (const float*)d_in[8];
    float* out = (float*)d_out;

    __half *xf, *Qf, *Kf, *Vf, *Of, *Wqf, *Wkf, *Wvf, *Wof;
    cudaGetSymbolAddress((void**)&xf, g_xf);
    cudaGetSymbolAddress((void**)&Qf, g_Qf);
    cudaGetSymbolAddress((void**)&Kf, g_Kf);
    cudaGetSymbolAddress((void**)&Vf, g_Vf);
    cudaGetSymbolAddress((void**)&Of, g_Of);
    cudaGetSymbolAddress((void**)&Wqf, g_Wqf);
    cudaGetSymbolAddress((void**)&Wkf, g_Wkf);
    cudaGetSymbolAddress((void**)&Wvf, g_Wvf);
    cudaGetSymbolAddress((void**)&Wof, g_Wof);

    // fused conversions: x (2M elems) + all 4 weights (1M each, guarded)
    convert_all<<<dim3(NTOK * DM / 1024, 1, 5), 256>>>(
        x, Wq, Wk, Wv, Wo, xf, Wqf, Wkf, Wvf, Wof);

    // fused QKV projections: 128x64 tiles -> grid (16, 16, 3) = 768 CTAs
    gemm_f16<false><<<dim3(DM / 64, NTOK / 128, 3), 256>>>(
        xf, Wqf, Wkf, Wvf, bq, bk, bv, Qf, Kf, Vf, nullptr);

    // attention
    flash_f16<<<dim3(NH, 32), 128, F_SMEM_B>>>(Qf, Kf, Vf, Of);

    // output projection -> fp32 result: grid (16, 16, 1) = 256 CTAs
    gemm_f16<true><<<dim3(DM / 64, NTOK / 128, 1), 256>>>(
        Of, Wof, nullptr, nullptr, bo, nullptr, nullptr, nullptr, nullptr, nullptr, out);
}

// round 16
// speedup vs baseline: 1.1113x; 1.1113x over previous
#include <cuda_runtime.h>
#include <cuda_fp16.h>
#include <cstdint>
#include <float.h>

#define NTOK 2048
#define DM   1024
#define NH   16
#define HD   64

// ---------------------------------------------------------------------------
// Scratch (__device__ globals; allocation-free rule)
// ---------------------------------------------------------------------------
__device__ __half g_xf[NTOK * DM];            // x in fp16
__device__ __half g_Qf[NTOK * DM];            // pre-scaled by 0.125*log2e
__device__ __half g_Kf[NTOK * DM];
__device__ __half g_Vf[NTOK * DM];
__device__ __half g_Of[NTOK * DM];            // attention output in fp16
// weights in fp16, ORIGINAL [K,N] layout
__device__ __half g_Wqf[DM * DM], g_Wkf[DM * DM], g_Wvf[DM * DM], g_Wof[DM * DM];

// ---------------------------------------------------------------------------
// PTX helpers (base-target tensor path; tcgen05 unavailable at compute_103)
// ---------------------------------------------------------------------------
__device__ __forceinline__ uint32_t smem_u32(const void* p) {
    uint32_t a;
    asm("{ .reg .u64 t; cvta.to.shared.u64 t, %1; cvt.u32.u64 %0, t; }" : "=r"(a) : "l"(p));
    return a;
}

__device__ __forceinline__ float ex2f(float x) {   // MUFU.EX2 (2^x)
    float r;
    asm("ex2.approx.ftz.f32 %0, %1;" : "=f"(r) : "f"(x));
    return r;
}

#define LDMATRIX_X4(r0, r1, r2, r3, addr) \
    asm volatile("ldmatrix.sync.aligned.m8n8.x4.shared.b16 {%0,%1,%2,%3}, [%4];" \
                 : "=r"(r0), "=r"(r1), "=r"(r2), "=r"(r3) : "r"(addr))
#define LDMATRIX_X4T(r0, r1, r2, r3, addr) \
    asm volatile("ldmatrix.sync.aligned.m8n8.x4.trans.shared.b16 {%0,%1,%2,%3}, [%4];" \
                 : "=r"(r0), "=r"(r1), "=r"(r2), "=r"(r3) : "r"(addr))
#define MMA_F16(d, a, b) \
    asm volatile("mma.sync.aligned.m16n8k16.row.col.f32.f16.f16.f32 " \
                 "{%0,%1,%2,%3}, {%4,%5,%6,%7}, {%8,%9}, {%0,%1,%2,%3};" \
                 : "+f"((d)[0]), "+f"((d)[1]), "+f"((d)[2]), "+f"((d)[3]) \
                 : "r"((a)[0]), "r"((a)[1]), "r"((a)[2]), "r"((a)[3]), \
                   "r"((b)[0]), "r"((b)[1]))

#define CP_ASYNC16(dst, src) \
    asm volatile("cp.async.cg.shared.global [%0], [%1], 16;" :: "r"(dst), "l"(src) : "memory")
#define CP_COMMIT() asm volatile("cp.async.commit_group;" ::: "memory")
#define CP_WAIT1()  asm volatile("cp.async.wait_group 1;" ::: "memory")

__device__ __forceinline__ uint32_t pack_h2(float a, float b) {
    __half2 t = __floats2half2_rn(a, b);
    return *reinterpret_cast<uint32_t*>(&t);
}

// 0.125 * log2(e): folded into Q so softmax runs in exp2 domain
#define QSCALE 0.18033688011112042f

// ---------------------------------------------------------------------------
// Fused fp32 -> fp16 conversion: z=0 -> x (2M elems), z=1..4 -> weights (1M).
// ---------------------------------------------------------------------------
__global__ __launch_bounds__(256)
void convert_all(const float* __restrict__ x,
                 const float* __restrict__ W0, const float* __restrict__ W1,
                 const float* __restrict__ W2, const float* __restrict__ W3,
                 __half* __restrict__ xf,
                 __half* __restrict__ T0, __half* __restrict__ T1,
                 __half* __restrict__ T2, __half* __restrict__ T3)
{
    const int z = blockIdx.z;
    if (z > 0 && blockIdx.x >= DM * DM / 1024) return;   // weights: 1M elems only
    const float* S = (z == 0) ? x : (z == 1) ? W0 : (z == 2) ? W1 : (z == 3) ? W2 : W3;
    __half* D      = (z == 0) ? xf : (z == 1) ? T0 : (z == 2) ? T1 : (z == 3) ? T2 : T3;
    int i4 = blockIdx.x * 256 + threadIdx.x;
    float4 v = reinterpret_cast<const float4*>(S)[i4];
    uint2 o;
    o.x = pack_h2(v.x, v.y);
    o.y = pack_h2(v.z, v.w);
    reinterpret_cast<uint2*>(D)[i4] = o;
}

// ---------------------------------------------------------------------------
// fp16 GEMM via mma.sync + 3-stage cp.async pipeline.
// C = A[M,K] @ B + bias, B in [K,N] layout (fragments via ldmatrix.trans).
// CTA tile: 128(M) x BN(N), BK=32, 256 threads, 2 CTAs/SM.
//   MT=4 -> BN=128 (2x4 warps, 64x32 warp tile)   [QKV: low re-read traffic]
//   MT=2 -> BN=64  (4x2 warps, 32x32 warp tile)   [out-proj: enough CTAs]
// z selects (B, bias, out); z==0 non-F32OUT (Q) scaled by QSCALE.
// ---------------------------------------------------------------------------
#define ASTRIDE 40                        // halfs per A smem row (32 + 8 pad)
#define ABYTES  (128 * ASTRIDE * 2)       // 10240
#define NSTAGE  3

template<int MT, bool F32OUT>
__global__ __launch_bounds__(256, 2)
void gemm_f16(const __half* __restrict__ A,
              const __half* __restrict__ B0, const __half* __restrict__ B1,
              const __half* __restrict__ B2,
              const float* __restrict__ bias0, const float* __restrict__ bias1,
              const float* __restrict__ bias2,
              __half* __restrict__ Ch0, __half* __restrict__ Ch1,
              __half* __restrict__ Ch2, float* __restrict__ Cf)
{
    constexpr int WARPS_M = 128 / (MT * 16);     // 2 (MT=4) or 4 (MT=2)
    constexpr int WARPS_N = 8 / WARPS_M;         // 4 or 2
    constexpr int BN      = WARPS_N * 32;        // 128 or 64
    constexpr int BSTR    = BN + 8;              // B smem row stride (halfs)
    constexpr int BBYTES  = 32 * BSTR * 2;
    constexpr int STAGEB  = ABYTES + BBYTES;
    constexpr int CPR     = BN / 8;              // 16B chunks per B k-row

    extern __shared__ __align__(16) char smx[];

    const int z = blockIdx.z;
    const __half* B    = (z == 0) ? B0 : (z == 1) ? B1 : B2;
    const float* bias  = (z == 0) ? bias0 : (z == 1) ? bias1 : bias2;
    __half* Ch         = (z == 0) ? Ch0 : (z == 1) ? Ch1 : Ch2;
    const float osc    = (!F32OUT && z == 0) ? QSCALE : 1.0f;

    const int tid  = threadIdx.x;
    const int wid  = tid >> 5, lane = tid & 31;
    const int wm   = wid / WARPS_N, wn = wid % WARPS_N;
    const int col0 = blockIdx.x * BN;
    const int row0 = blockIdx.y * 128;

    const uint32_t sbase = smem_u32(smx);

    // A staging: 512 16B-chunks; thread t -> chunks t, t+256
    const int at_r0 = (tid + 0)   >> 2, at_c0 = ((tid + 0)   & 3) << 3;
    const int at_r1 = (tid + 256) >> 2, at_c1 = ((tid + 256) & 3) << 3;
    const __half* Ap0 = A + (size_t)(row0 + at_r0) * DM + at_c0;
    const __half* Ap1 = A + (size_t)(row0 + at_r1) * DM + at_c1;
    const uint32_t ad0 = (uint32_t)(at_r0 * ASTRIDE + at_c0) * 2;
    const uint32_t ad1 = (uint32_t)(at_r1 * ASTRIDE + at_c1) * 2;

    // B staging: 4*BN chunks (512 for BN=128 -> 2/thread; 256 for BN=64 -> 1/thread)
    const int b0_r = tid / CPR,        b0_c = (tid % CPR) * 8;
    const int b1_r = (tid + 256) / CPR, b1_c = ((tid + 256) % CPR) * 8;
    const __half* Bp0 = B + (size_t)b0_r * DM + col0 + b0_c;
    const __half* Bp1 = B + (size_t)b1_r * DM + col0 + b1_c;
    const uint32_t bd0 = (uint32_t)(b0_r * BSTR + b0_c) * 2;
    const uint32_t bd1 = (uint32_t)(b1_r * BSTR + b1_c) * 2;

    auto issue_stage = [&](int stage, int k0) {
        const uint32_t sD = sbase + stage * STAGEB;
        CP_ASYNC16(sD + ad0,          Ap0 + k0);
        CP_ASYNC16(sD + ad1,          Ap1 + k0);
        CP_ASYNC16(sD + ABYTES + bd0, Bp0 + (size_t)k0 * DM);
        if (WARPS_N == 4)
            CP_ASYNC16(sD + ABYTES + bd1, Bp1 + (size_t)k0 * DM);
    };

    // prologue: prefill stages 0, 1
    issue_stage(0, 0);  CP_COMMIT();
    issue_stage(1, 32); CP_COMMIT();

    // fragment offsets
    const int aRow  = wm * MT * 16 + (lane & 15);
    const int aK8   = (lane >> 4) << 3;
    const int bRowL = lane & 15;
    const int bC8   = (lane >> 4) << 3;

    float acc[MT][4][4] = {};

    #pragma unroll 1
    for (int c = 0; c < DM / 32; c++) {
        CP_WAIT1();
        __syncthreads();

        const uint32_t sA = sbase + (c % NSTAGE) * STAGEB;
        const uint32_t sB = sA + ABYTES;

        #pragma unroll
        for (int ks = 0; ks < 32; ks += 16) {
            uint32_t bf[8];
            #pragma unroll
            for (int g = 0; g < 2; g++) {
                uint32_t off = sB + (uint32_t)(((ks + bRowL) * BSTR
                                 + wn * 32 + g * 16 + bC8) * 2);
                LDMATRIX_X4T(bf[4 * g], bf[4 * g + 1], bf[4 * g + 2], bf[4 * g + 3], off);
            }
            #pragma unroll
            for (int mt = 0; mt < MT; mt++) {
                uint32_t af[4];
                uint32_t off = sA + (uint32_t)(((aRow + mt * 16) * ASTRIDE + ks + aK8) * 2);
                LDMATRIX_X4(af[0], af[1], af[2], af[3], off);
                #pragma unroll
                for (int nt = 0; nt < 4; nt++) MMA_F16(acc[mt][nt], af, &bf[nt * 2]);
            }
        }

        // issue stage c+2 into buffer (c+2)%3 (all warps past this iter's sync)
        if (c + 2 < DM / 32)
            issue_stage((c + 2) % NSTAGE, (c + 2) * 32);
        CP_COMMIT();
    }

    // epilogue
    const int qr = lane >> 2, qc = (lane & 3) << 1;
    #pragma unroll
    for (int nt = 0; nt < 4; nt++) {
        const int col = col0 + wn * 32 + nt * 8 + qc;
        const float2 bb = *reinterpret_cast<const float2*>(&bias[col]);
        #pragma unroll
        for (int mt = 0; mt < MT; mt++) {
            const int r = row0 + wm * MT * 16 + mt * 16 + qr;
            float v00 = (acc[mt][nt][0] + bb.x) * osc, v01 = (acc[mt][nt][1] + bb.y) * osc;
            float v10 = (acc[mt][nt][2] + bb.x) * osc, v11 = (acc[mt][nt][3] + bb.y) * osc;
            if (F32OUT) {
                float2 o0 = { v00, v01 }, o1 = { v10, v11 };
                *reinterpret_cast<float2*>(&Cf[(size_t)r * DM + col])       = o0;
                *reinterpret_cast<float2*>(&Cf[(size_t)(r + 8) * DM + col]) = o1;
            } else {
                *reinterpret_cast<uint32_t*>(&Ch[(size_t)r * DM + col])       = pack_h2(v00, v01);
                *reinterpret_cast<uint32_t*>(&Ch[(size_t)(r + 8) * DM + col]) = pack_h2(v10, v11);
            }
        }
    }
}

// ---------------------------------------------------------------------------
// fp16 flash attention (causal), exp2-domain softmax (Q pre-scaled).
// CTA = 64 q-rows x 1 head, 128 threads (4 warps x 16 rows); K-tile = 64.
// Dense/diagonal split: tiles kb < qb have NO masks or predicates.
// ---------------------------------------------------------------------------
#define FSTR 72   // smem row stride (halfs)
#define F_Q        0
#define F_K(b)     ((64  + (b) * 128) * FSTR)
#define F_V(b)     ((128 + (b) * 128) * FSTR)
#define F_SMEM_B   (320 * FSTR * 2)   // 46080 B

template<bool DIAG>
__device__ __forceinline__ void fa_tile(
    const int kb, const int warpR, const int lane,
    const uint32_t (&qf)[4][4], const uint32_t sK, const uint32_t sV,
    float (&o)[8][4], float& m0, float& m1, float& l0, float& l1)
{
    float s[8][4];
    #pragma unroll
    for (int nt = 0; nt < 8; nt++) {
        float init = 0.f;
        if (DIAG) init = ((kb * 64 + nt * 8) <= (warpR + 15)) ? 0.f : -1e30f;
        s[nt][0] = init; s[nt][1] = init; s[nt][2] = init; s[nt][3] = init;
    }

    #pragma unroll
    for (int kc = 0; kc < 4; kc++) {
        uint32_t kf[16];
        #pragma unroll
        for (int np = 0; np < 4; np++) {
            if (!DIAG || (kb * 64 + np * 16) <= (warpR + 15)) {
                uint32_t off = sK + (uint32_t)(((np * 16 + ((lane >> 4) << 3) + (lane & 7)) * FSTR
                                 + kc * 16 + (((lane >> 3) & 1) << 3)) * 2);
                LDMATRIX_X4(kf[4 * np], kf[4 * np + 1], kf[4 * np + 2], kf[4 * np + 3], off);
            }
        }
        #pragma unroll
        for (int nt = 0; nt < 8; nt++)
            if (!DIAG || (kb * 64 + nt * 8) <= (warpR + 15))
                MMA_F16(s[nt], qf[kc], &kf[nt * 2]);
    }

    if (DIAG) {
        #pragma unroll
        for (int nt = 0; nt < 8; nt++) {
            if ((kb * 64 + nt * 8) <= (warpR + 15)) {
                const int colg = kb * 64 + nt * 8 + ((lane & 3) << 1);
                const int r0g  = warpR + (lane >> 2);
                #pragma unroll
                for (int j = 0; j < 4; j++) {
                    int colj = colg + (j & 1);
                    int rowj = r0g + ((j >> 1) << 3);
                    if (colj > rowj) s[nt][j] = -1e30f;
                }
            }
        }
    }

    float rm0 = -1e30f, rm1 = -1e30f;
    #pragma unroll
    for (int nt = 0; nt < 8; nt++) {
        rm0 = fmaxf(rm0, fmaxf(s[nt][0], s[nt][1]));
        rm1 = fmaxf(rm1, fmaxf(s[nt][2], s[nt][3]));
    }
    rm0 = fmaxf(rm0, __shfl_xor_sync(0xffffffffu, rm0, 1));
    rm0 = fmaxf(rm0, __shfl_xor_sync(0xffffffffu, rm0, 2));
    rm1 = fmaxf(rm1, __shfl_xor_sync(0xffffffffu, rm1, 1));
    rm1 = fmaxf(rm1, __shfl_xor_sync(0xffffffffu, rm1, 2));

    const float mn0 = fmaxf(m0, rm0), mn1 = fmaxf(m1, rm1);
    const float cr0 = ex2f(m0 - mn0), cr1 = ex2f(m1 - mn1);
    m0 = mn0; m1 = mn1;

    float rs0 = 0.f, rs1 = 0.f;
    #pragma unroll
    for (int nt = 0; nt < 8; nt++) {
        s[nt][0] = ex2f(s[nt][0] - mn0);
        s[nt][1] = ex2f(s[nt][1] - mn0);
        s[nt][2] = ex2f(s[nt][2] - mn1);
        s[nt][3] = ex2f(s[nt][3] - mn1);
        rs0 += s[nt][0] + s[nt][1];
        rs1 += s[nt][2] + s[nt][3];
    }
    rs0 += __shfl_xor_sync(0xffffffffu, rs0, 1);
    rs0 += __shfl_xor_sync(0xffffffffu, rs0, 2);
    rs1 += __shfl_xor_sync(0xffffffffu, rs1, 1);
    rs1 += __shfl_xor_sync(0xffffffffu, rs1, 2);
    l0 = l0 * cr0 + rs0;
    l1 = l1 * cr1 + rs1;

    #pragma unroll
    for (int nt = 0; nt < 8; nt++) {
        o[nt][0] *= cr0; o[nt][1] *= cr0;
        o[nt][2] *= cr1; o[nt][3] *= cr1;
    }

    #pragma unroll
    for (int kc = 0; kc < 4; kc++) {
        if (!DIAG || (kb * 64 + kc * 16) <= (warpR + 15)) {
            uint32_t pf[4];
            pf[0] = pack_h2(s[2 * kc][0],     s[2 * kc][1]);
            pf[1] = pack_h2(s[2 * kc][2],     s[2 * kc][3]);
            pf[2] = pack_h2(s[2 * kc + 1][0], s[2 * kc + 1][1]);
            pf[3] = pack_h2(s[2 * kc + 1][2], s[2 * kc + 1][3]);

            uint32_t vf[16];
            #pragma unroll
            for (int np = 0; np < 4; np++) {
                uint32_t off = sV + (uint32_t)(((kc * 16 + (lane & 15)) * FSTR
                                 + np * 16 + ((lane >> 4) << 3)) * 2);
                LDMATRIX_X4T(vf[4 * np], vf[4 * np + 1], vf[4 * np + 2], vf[4 * np + 3], off);
            }
            #pragma unroll
            for (int nt = 0; nt < 8; nt++) MMA_F16(o[nt], pf, &vf[nt * 2]);
        }
    }
}

__global__ __launch_bounds__(128, 2)
void flash_f16(const __half* __restrict__ Qg, const __half* __restrict__ Kg,
               const __half* __restrict__ Vg, __half* __restrict__ Og)
{
    extern __shared__ __half fsm[];

    const int h     = blockIdx.x;
    const int qb    = 31 - blockIdx.y;     // big tiles first
    const int tid   = threadIdx.x;
    const int wid   = tid >> 5, lane = tid & 31;
    const int cb    = h * HD;
    const int row0  = qb * 64;
    const int kbmax = qb;                  // diagonal tile index
    const int warpR = row0 + wid * 16;

    const uint32_t sb = smem_u32(fsm);
    char* smc = reinterpret_cast<char*>(fsm);

    size_t   gkv[4];
    uint32_t kvd[4];
    #pragma unroll
    for (int s = 0; s < 4; s++) {
        int vid = tid + 128 * s;
        int r = vid >> 3, c8 = (vid & 7) << 3;
        gkv[s] = (size_t)r * DM + cb + c8;
        kvd[s] = (uint32_t)(r * FSTR + c8) * 2;
    }

    #pragma unroll
    for (int s = 0; s < 4; s++) {
        uint4 v = *reinterpret_cast<const uint4*>(Qg + (size_t)row0 * DM + gkv[s]);
        *reinterpret_cast<uint4*>(smc + F_Q * 2 + kvd[s]) = v;
    }

    uint4 pk[4], pv[4];
    #pragma unroll
    for (int s = 0; s < 4; s++) {
        pk[s] = *reinterpret_cast<const uint4*>(Kg + gkv[s]);
        pv[s] = *reinterpret_cast<const uint4*>(Vg + gkv[s]);
    }
    #pragma unroll
    for (int s = 0; s < 4; s++) {
        *reinterpret_cast<uint4*>(smc + F_K(0) * 2 + kvd[s]) = pk[s];
        *reinterpret_cast<uint4*>(smc + F_V(0) * 2 + kvd[s]) = pv[s];
    }
    __syncthreads();

    uint32_t qf[4][4];
    {
        uint32_t off = sb + F_Q * 2
            + (uint32_t)(((wid * 16 + (lane & 15)) * FSTR + ((lane >> 4) << 3)) * 2);
        #pragma unroll
        for (int kc = 0; kc < 4; kc++)
            LDMATRIX_X4(qf[kc][0], qf[kc][1], qf[kc][2], qf[kc][3], off + kc * 32);
    }

    float m0 = -1e30f, m1 = -1e30f, l0 = 0.f, l1 = 0.f;
    float o[8][4] = {};

    #pragma unroll 1
    for (int kb = 0; kb < kbmax; kb++) {
        const size_t nb = (size_t)((kb + 1) * 64) * DM;
        #pragma unroll
        for (int s = 0; s < 4; s++) {
            pk[s] = *reinterpret_cast<const uint4*>(Kg + nb + gkv[s]);
            pv[s] = *reinterpret_cast<const uint4*>(Vg + nb + gkv[s]);
        }

        fa_tile<false>(kb, warpR, lane, qf,
                       sb + F_K(kb & 1) * 2, sb + F_V(kb & 1) * 2,
                       o, m0, m1, l0, l1);

        char* dk = smc + F_K((kb + 1) & 1) * 2;
        char* dv = smc + F_V((kb + 1) & 1) * 2;
        #pragma unroll
        for (int s2 = 0; s2 < 4; s2++) {
            *reinterpret_cast<uint4*>(dk + kvd[s2]) = pk[s2];
            *reinterpret_cast<uint4*>(dv + kvd[s2]) = pv[s2];
        }
        __syncthreads();
    }

    fa_tile<true>(kbmax, warpR, lane, qf,
                  sb + F_K(kbmax & 1) * 2, sb + F_V(kbmax & 1) * 2,
                  o, m0, m1, l0, l1);

    const float inv0 = 1.f / l0, inv1 = 1.f / l1;
    const int r0g = warpR + (lane >> 2);
    #pragma unroll
    for (int nt = 0; nt < 8; nt++) {
        const int col = cb + nt * 8 + ((lane & 3) << 1);
        *reinterpret_cast<uint32_t*>(&Og[(size_t)r0g * DM + col]) =
            pack_h2(o[nt][0] * inv0, o[nt][1] * inv0);
        *reinterpret_cast<uint32_t*>(&Og[(size_t)(r0g + 8) * DM + col]) =
            pack_h2(o[nt][2] * inv1, o[nt][3] * inv1);
    }
}

// ---------------------------------------------------------------------------
// Launch
// ---------------------------------------------------------------------------
#define GSMEM_QKV  (NSTAGE * (ABYTES + 32 * (128 + 8) * 2))   // 56832
#define GSMEM_OUT  (NSTAGE * (ABYTES + 32 * (64 + 8) * 2))    // 44544

extern "C" void kernel_launch(void* const* d_in, const int* in_sizes, int n_in,
                              void* d_out, int out_size)
{
    const float* x  = (const float*)d_in[0];
    const float* Wq = (const float*)d_in[1];
    const float* bq = (const float*)d_in[2];
    const float* Wk = (const float*)d_in[3];
    const float* bk = (const float*)d_in[4];
    const float* Wv = (const float*)d_in[5];
    const float* bv = (const float*)d_in[6];
    const float* Wo = (const float*)d_in[7];
    const float* bo = (const float*)d_in[8];
    float* out = (float*)d_out;

    __half *xf, *Qf, *Kf, *Vf, *Of, *Wqf, *Wkf, *Wvf, *Wof;
    cudaGetSymbolAddress((void**)&xf, g_xf);
    cudaGetSymbolAddress((void**)&Qf, g_Qf);
    cudaGetSymbolAddress((void**)&Kf, g_Kf);
    cudaGetSymbolAddress((void**)&Vf, g_Vf);
    cudaGetSymbolAddress((void**)&Of, g_Of);
    cudaGetSymbolAddress((void**)&Wqf, g_Wqf);
    cudaGetSymbolAddress((void**)&Wkf, g_Wkf);
    cudaGetSymbolAddress((void**)&Wvf, g_Wvf);
    cudaGetSymbolAddress((void**)&Wof, g_Wof);

    cudaFuncSetAttribute(gemm_f16<4, false>,
                         cudaFuncAttributeMaxDynamicSharedMemorySize, GSMEM_QKV);

    // fused conversions: x (2M elems) + all 4 weights (1M each, guarded)
    convert_all<<<dim3(NTOK * DM / 1024, 1, 5), 256>>>(
        x, Wq, Wk, Wv, Wo, xf, Wqf, Wkf, Wvf, Wof);

    // fused QKV projections: 128x128 tiles -> grid (8, 16, 3) = 384 CTAs
    gemm_f16<4, false><<<dim3(DM / 128, NTOK / 128, 3), 256, GSMEM_QKV>>>(
        xf, Wqf, Wkf, Wvf, bq, bk, bv, Qf, Kf, Vf, nullptr);

    // attention
    flash_f16<<<dim3(NH, 32), 128, F_SMEM_B>>>(Qf, Kf, Vf, Of);

    // output projection: 128x64 tiles -> grid (16, 16, 1) = 256 CTAs
    gemm_f16<2, true><<<dim3(DM / 64, NTOK / 128, 1), 256, GSMEM_OUT>>>(
        Of, Wof, nullptr, nullptr, bo, nullptr, nullptr, nullptr, nullptr, nullptr, out);
}